// round 2
// baseline (speedup 1.0000x reference)
#include <cuda_runtime.h>
#include <cstdint>

// Problem constants (fixed shapes per reference)
#define N_NODES 100000
#define D_FEAT  64
#define OUT_COLS 65          // D + 1
#define PAD_COLS 68          // padded so row stride (68*4=272B) is 16B-aligned

// Scratch accumulator: [N_NODES, PAD_COLS] float (27.2 MB). Static __device__
// array — allowed under the allocation guards.
__device__ float g_scratch[(size_t)N_NODES * PAD_COLS];

// ---------------------------------------------------------------------------
// Kernel 1: zero the scratch accumulator (float4 stores)
// ---------------------------------------------------------------------------
__global__ void zero_scratch_kernel() {
    const size_t total4 = (size_t)N_NODES * PAD_COLS / 4;   // 1,700,000
    size_t i = (size_t)blockIdx.x * blockDim.x + threadIdx.x;
    float4* p = reinterpret_cast<float4*>(g_scratch);
    if (i < total4) {
        p[i] = make_float4(0.f, 0.f, 0.f, 0.f);
    }
}

// ---------------------------------------------------------------------------
// Vectorized global reductions. Addresses converted to global space
// explicitly (cvta) before use with the .global-qualified red op.
// ---------------------------------------------------------------------------
__device__ __forceinline__ void red_add_v4(float* addr, float4 v) {
    unsigned long long gaddr;
    asm volatile("cvta.to.global.u64 %0, %1;" : "=l"(gaddr) : "l"(addr));
    asm volatile("red.global.add.v4.f32 [%0], {%1, %2, %3, %4};"
                 :: "l"(gaddr), "f"(v.x), "f"(v.y), "f"(v.z), "f"(v.w)
                 : "memory");
}

__device__ __forceinline__ void red_add_f32(float* addr, float v) {
    unsigned long long gaddr;
    asm volatile("cvta.to.global.u64 %0, %1;" : "=l"(gaddr) : "l"(addr));
    asm volatile("red.global.add.f32 [%0], %1;"
                 :: "l"(gaddr), "f"(v)
                 : "memory");
}

// ---------------------------------------------------------------------------
// Kernel 2: scatter-add. 16 threads cooperate on one edge.
//   lane l loads float4 #l of the src row (64 floats = 16 x float4)
//   and issues red.global.add.v4.f32 into the dst row of g_scratch.
//   lane 0 additionally adds e_feat into column 64.
// ---------------------------------------------------------------------------
__global__ void scatter_kernel(const float* __restrict__ emb,
                               const float* __restrict__ e_feat,
                               const int*   __restrict__ src_idx,
                               const int*   __restrict__ dst_idx,
                               int E) {
    const long long t = (long long)blockIdx.x * blockDim.x + threadIdx.x;
    const long long edge = t >> 4;    // 16 threads per edge
    const int lane = (int)(t & 15);
    if (edge >= E) return;

    const int s = __ldg(src_idx + edge);
    const int d = __ldg(dst_idx + edge);

    const float4 v = __ldg(reinterpret_cast<const float4*>(emb + (size_t)s * D_FEAT) + lane);

    float* dst_row = g_scratch + (size_t)d * PAD_COLS;
    red_add_v4(dst_row + lane * 4, v);

    if (lane == 0) {
        red_add_f32(dst_row + D_FEAT, __ldg(e_feat + edge));
    }
}

// ---------------------------------------------------------------------------
// Kernel 3: repack [N, PAD_COLS] scratch -> [N, OUT_COLS] output
// Coalesced on the output side.
// ---------------------------------------------------------------------------
__global__ void repack_kernel(float* __restrict__ out) {
    const size_t total = (size_t)N_NODES * OUT_COLS;
    size_t i = (size_t)blockIdx.x * blockDim.x + threadIdx.x;
    if (i < total) {
        size_t n = i / OUT_COLS;
        size_t c = i - n * OUT_COLS;
        out[i] = g_scratch[n * PAD_COLS + c];
    }
}

// ---------------------------------------------------------------------------
// Launch
// ---------------------------------------------------------------------------
extern "C" void kernel_launch(void* const* d_in, const int* in_sizes, int n_in,
                              void* d_out, int out_size) {
    const float* emb     = (const float*)d_in[0];   // [N, 64]
    const float* e_feat  = (const float*)d_in[1];   // [E]
    const int*   src_idx = (const int*)d_in[2];     // [E]
    const int*   dst_idx = (const int*)d_in[3];     // [E]
    float*       out     = (float*)d_out;           // [N, 65]

    const int E = in_sizes[1];

    // 1) zero scratch
    {
        const size_t total4 = (size_t)N_NODES * PAD_COLS / 4;
        int threads = 256;
        int blocks  = (int)((total4 + threads - 1) / threads);
        zero_scratch_kernel<<<blocks, threads>>>();
    }

    // 2) scatter
    if (E > 0) {
        const long long total_threads = (long long)E * 16;
        int threads = 256;
        int blocks  = (int)((total_threads + threads - 1) / threads);
        scatter_kernel<<<blocks, threads>>>(emb, e_feat, src_idx, dst_idx, E);
    }

    // 3) repack to output layout
    {
        const size_t total = (size_t)N_NODES * OUT_COLS;
        int threads = 256;
        int blocks  = (int)((total + threads - 1) / threads);
        repack_kernel<<<blocks, threads>>>(out);
    }
}

// round 3
// speedup vs baseline: 2.3366x; 2.3366x over previous
#include <cuda_runtime.h>
#include <cstdint>

// Problem constants (fixed shapes per reference)
#define N_NODES  100000
#define D_FEAT   64
#define OUT_COLS 65
#define MAXDEG   48            // Poisson(12) max over 100K nodes ~35; 48 is safe margin
#define OVF_CAP  1300000       // >= E, so overflow list can never drop edges

// Static scratch (allocation-guard-safe)
__device__ int  g_count[N_NODES];                       // per-node degree counters
__device__ int  g_ovf_count;                            // overflow edge count
__device__ int  g_ovf_edges[OVF_CAP];                   // overflow edge indices
__device__ int2 g_slots[(size_t)N_NODES * MAXDEG];      // {src_idx, bitcast(e_feat)} per slot

// ---------------------------------------------------------------------------
// Kernel 1: zero counters
// ---------------------------------------------------------------------------
__global__ void zero_counters_kernel() {
    int i = blockIdx.x * blockDim.x + threadIdx.x;
    if (i < N_NODES) g_count[i] = 0;
    if (i == 0) g_ovf_count = 0;
}

// ---------------------------------------------------------------------------
// Kernel 2: bin edges by destination node into padded slots.
// One thread per edge. Int atomics only.
// ---------------------------------------------------------------------------
__global__ void bin_kernel(const float* __restrict__ e_feat,
                           const int*   __restrict__ src_idx,
                           const int*   __restrict__ dst_idx,
                           int E) {
    int e = blockIdx.x * blockDim.x + threadIdx.x;
    if (e >= E) return;

    const int d = __ldg(dst_idx + e);
    const int pos = atomicAdd(&g_count[d], 1);
    if (pos < MAXDEG) {
        int2 se;
        se.x = __ldg(src_idx + e);
        se.y = __float_as_int(__ldg(e_feat + e));
        g_slots[(size_t)d * MAXDEG + pos] = se;
    } else {
        int oi = atomicAdd(&g_ovf_count, 1);
        if (oi < OVF_CAP) g_ovf_edges[oi] = e;
    }
}

// ---------------------------------------------------------------------------
// Kernel 3: accumulate. 16 lanes per node; lane l owns float4 column chunk l.
// Writes the FULL output row (all 65 cols) -> no pre-zeroing of d_out needed.
// No atomics.
// ---------------------------------------------------------------------------
__global__ void accum_kernel(const float* __restrict__ emb,
                             float* __restrict__ out) {
    const int t    = blockIdx.x * blockDim.x + threadIdx.x;
    const int node = t >> 4;
    const int lane = t & 15;
    if (node >= N_NODES) return;

    int deg = g_count[node];
    if (deg > MAXDEG) deg = MAXDEG;

    const int2* slots = g_slots + (size_t)node * MAXDEG;

    float4 acc = make_float4(0.f, 0.f, 0.f, 0.f);
    float  accE = 0.f;

    // Unroll by 2 for a little MLP on the gather
    int j = 0;
    for (; j + 1 < deg; j += 2) {
        const int2 se0 = slots[j];
        const int2 se1 = slots[j + 1];
        const float4 v0 = __ldg(reinterpret_cast<const float4*>(emb + (size_t)se0.x * D_FEAT) + lane);
        const float4 v1 = __ldg(reinterpret_cast<const float4*>(emb + (size_t)se1.x * D_FEAT) + lane);
        acc.x += v0.x + v1.x;
        acc.y += v0.y + v1.y;
        acc.z += v0.z + v1.z;
        acc.w += v0.w + v1.w;
        accE  += __int_as_float(se0.y) + __int_as_float(se1.y);
    }
    if (j < deg) {
        const int2 se = slots[j];
        const float4 v = __ldg(reinterpret_cast<const float4*>(emb + (size_t)se.x * D_FEAT) + lane);
        acc.x += v.x; acc.y += v.y; acc.z += v.z; acc.w += v.w;
        accE  += __int_as_float(se.y);
    }

    float* row = out + (size_t)node * OUT_COLS + lane * 4;
    row[0] = acc.x;
    row[1] = acc.y;
    row[2] = acc.z;
    row[3] = acc.w;
    if (lane == 0) out[(size_t)node * OUT_COLS + D_FEAT] = accE;
}

// ---------------------------------------------------------------------------
// Kernel 4: overflow fix-up (normally a no-op). Runs AFTER accum's full-row
// writes; adds overflow-edge contributions with scalar atomics.
// ---------------------------------------------------------------------------
__global__ void ovf_fix_kernel(const float* __restrict__ emb,
                               const float* __restrict__ e_feat,
                               const int*   __restrict__ src_idx,
                               const int*   __restrict__ dst_idx,
                               float* __restrict__ out) {
    int n = g_ovf_count;
    if (n > OVF_CAP) n = OVF_CAP;
    const int total = n * 16;
    for (int t = blockIdx.x * blockDim.x + threadIdx.x; t < total;
         t += gridDim.x * blockDim.x) {
        const int i    = t >> 4;
        const int lane = t & 15;
        const int e = g_ovf_edges[i];
        const int s = src_idx[e];
        const int d = dst_idx[e];
        const float4 v = __ldg(reinterpret_cast<const float4*>(emb + (size_t)s * D_FEAT) + lane);
        float* row = out + (size_t)d * OUT_COLS + lane * 4;
        atomicAdd(row + 0, v.x);
        atomicAdd(row + 1, v.y);
        atomicAdd(row + 2, v.z);
        atomicAdd(row + 3, v.w);
        if (lane == 0) atomicAdd(out + (size_t)d * OUT_COLS + D_FEAT, e_feat[e]);
    }
}

// ---------------------------------------------------------------------------
// Launch
// ---------------------------------------------------------------------------
extern "C" void kernel_launch(void* const* d_in, const int* in_sizes, int n_in,
                              void* d_out, int out_size) {
    const float* emb     = (const float*)d_in[0];   // [N, 64]
    const float* e_feat  = (const float*)d_in[1];   // [E]
    const int*   src_idx = (const int*)d_in[2];     // [E]
    const int*   dst_idx = (const int*)d_in[3];     // [E]
    float*       out     = (float*)d_out;           // [N, 65]

    const int E = in_sizes[1];

    // 1) zero counters
    {
        int threads = 256;
        int blocks  = (N_NODES + threads - 1) / threads;
        zero_counters_kernel<<<blocks, threads>>>();
    }

    // 2) bin edges by dst
    if (E > 0) {
        int threads = 256;
        int blocks  = (E + threads - 1) / threads;
        bin_kernel<<<blocks, threads>>>(e_feat, src_idx, dst_idx, E);
    }

    // 3) accumulate per node (writes full output)
    {
        const long long total = (long long)N_NODES * 16;
        int threads = 256;
        int blocks  = (int)((total + threads - 1) / threads);
        accum_kernel<<<blocks, threads>>>(emb, out);
    }

    // 4) overflow fix-up (normally no-op)
    if (E > 0) {
        ovf_fix_kernel<<<64, 256>>>(emb, e_feat, src_idx, dst_idx, out);
    }
}